// round 9
// baseline (speedup 1.0000x reference)
#include <cuda_runtime.h>
#include <math.h>

#define B_ 256
#define M_ 64
#define N_ 32
#define D_ 128
#define T_ 64
#define L_ 128

// Scratch (allocation-free: __device__ globals)
__device__ float g_WT[(size_t)M_ * N_ * D_ * T_];      // entmax weights, [mn][d][t]
__device__ float g_priors[(size_t)N_ * B_ * M_ * T_];  // priors, [n][b][m][t]
__device__ float g_lh[T_ * L_];                        // normalized leaves, TRANSPOSED [t][l]

// ---------------------------------------------------------------------------
// K0: normalize routing_leaves rows; store transposed [t][l]
// ---------------------------------------------------------------------------
__global__ void k_leaves(const float* __restrict__ leaves) {
    int l = threadIdx.x;
    if (l < L_) {
        float s = 0.f;
        #pragma unroll
        for (int t = 0; t < T_; ++t) { float v = leaves[l * T_ + t]; s = fmaf(v, v, s); }
        float inv = 1.0f / fmaxf(sqrtf(s), 1e-12f);
        #pragma unroll
        for (int t = 0; t < T_; ++t) g_lh[t * L_ + l] = leaves[l * T_ + t] * inv;
    }
}

// ---------------------------------------------------------------------------
// K1: exact 1.5-entmax over D per (m,n,t) column via 12 bisection + 2 Newton
//     on f(tau) = sum max(z - tau, 0)^2 = 1. 2 threads/column.
//     Output layout: g_WT[mn][d][t].
// ---------------------------------------------------------------------------
__global__ __launch_bounds__(128) void k_entmax(const float* __restrict__ rw) {
    __shared__ float sm[D_ * 65];  // [d][t] pad 65
    int mn = blockIdx.x;
    const float* src = rw + (size_t)mn * D_ * T_;
    for (int i = threadIdx.x; i < D_ * T_; i += 128)
        sm[(i >> 6) * 65 + (i & 63)] = src[i];
    __syncthreads();

    int col = threadIdx.x >> 1, half = threadIdx.x & 1;
    float z[64];
    float mx = -3.0e38f;
    #pragma unroll
    for (int k = 0; k < 64; ++k) {
        z[k] = sm[(half * 64 + k) * 65 + col];
        mx = fmaxf(mx, z[k]);
    }
    mx = fmaxf(mx, __shfl_xor_sync(0xffffffffu, mx, 1));
    #pragma unroll
    for (int k = 0; k < 64; ++k) z[k] = 0.5f * z[k] - 0.5f * mx;

    float lo = -1.0f, hi = 0.0f;
    #pragma unroll 1
    for (int it = 0; it < 12; ++it) {
        float mid = 0.5f * (lo + hi);
        float s0 = 0.f, s1 = 0.f, s2 = 0.f, s3 = 0.f;
        #pragma unroll
        for (int k = 0; k < 64; k += 4) {
            float a0 = fmaxf(z[k + 0] - mid, 0.f); s0 = fmaf(a0, a0, s0);
            float a1 = fmaxf(z[k + 1] - mid, 0.f); s1 = fmaf(a1, a1, s1);
            float a2 = fmaxf(z[k + 2] - mid, 0.f); s2 = fmaf(a2, a2, s2);
            float a3 = fmaxf(z[k + 3] - mid, 0.f); s3 = fmaf(a3, a3, s3);
        }
        float s = (s0 + s1) + (s2 + s3);
        s += __shfl_xor_sync(0xffffffffu, s, 1);
        if (s >= 1.0f) lo = mid; else hi = mid;
    }
    float tau = 0.5f * (lo + hi);
    #pragma unroll 1
    for (int it = 0; it < 2; ++it) {
        float f0 = 0.f, f1 = 0.f, g0 = 0.f, g1 = 0.f;
        #pragma unroll
        for (int k = 0; k < 64; k += 2) {
            float a0 = fmaxf(z[k + 0] - tau, 0.f); f0 = fmaf(a0, a0, f0); g0 += a0;
            float a1 = fmaxf(z[k + 1] - tau, 0.f); f1 = fmaf(a1, a1, f1); g1 += a1;
        }
        float f = f0 + f1, g = g0 + g1;
        f += __shfl_xor_sync(0xffffffffu, f, 1);
        g += __shfl_xor_sync(0xffffffffu, g, 1);
        tau += (f - 1.0f) / fmaxf(2.0f * g, 1e-12f);
    }

    #pragma unroll
    for (int k = 0; k < 64; ++k) {
        float a = fmaxf(z[k] - tau, 0.f);
        sm[(half * 64 + k) * 65 + col] = a * a;
    }
    __syncthreads();
    float* dst = g_WT + (size_t)mn * D_ * T_;  // [d][t]
    for (int i = threadIdx.x; i < D_ * T_; i += 128)
        dst[i] = sm[(i >> 6) * 65 + (i & 63)];
}

// ---------------------------------------------------------------------------
// K2: priors[b,m,n,t] = sum_d x[b,m,d] * W[m,n,d,t].
//     Grid = 2 * M_*N_: blockIdx = mn*2 + chunk (128 b's per block).
//     128 threads, tile 8 b x 8 t (t quads 4tx..+3, 32+4tx..+3).
//     x (global) prefetched one dq ahead; W staged [d][64] in smem.
//     Packed fma.rn.f32x2. Output [n][b][m][t].
// ---------------------------------------------------------------------------
__global__ __launch_bounds__(128, 3) void k_priors(const float* __restrict__ x) {
    __shared__ __align__(16) float ws[D_ * 64];  // [d][t], rows 256B
    int mn = blockIdx.x >> 1;
    int chunk = blockIdx.x & 1;
    int m = mn >> 5, n = mn & 31;
    {
        const float* wsrc = g_WT + (size_t)mn * D_ * T_;
        for (int i = threadIdx.x; i < D_ * T_; i += 128) ws[i] = wsrc[i];
    }
    __syncthreads();
    unsigned wsb = (unsigned)__cvta_generic_to_shared(ws);
    int tx = threadIdx.x & 7;    // t quads: 4tx..+3 and 32+4tx..+3
    int by = threadIdx.x >> 3;   // b-group (0..15), 8 b's each
    unsigned wA = wsb + (unsigned)tx * 16u;  // quad A
    unsigned wB = wA + 128u;                 // quad B (t+32)

    int b0 = chunk * 128 + by * 8;
    unsigned long long acc[8][4];
    #pragma unroll
    for (int bi = 0; bi < 8; ++bi)
        #pragma unroll
        for (int j = 0; j < 4; ++j) acc[bi][j] = 0ull;

    const float4* xr[8];
    #pragma unroll
    for (int bi = 0; bi < 8; ++bi)
        xr[bi] = reinterpret_cast<const float4*>(x + ((size_t)(b0 + bi) * M_ + m) * D_);

    float4 xv[8], xn[8];
    #pragma unroll
    for (int bi = 0; bi < 8; ++bi) xv[bi] = __ldg(&xr[bi][0]);

    #pragma unroll 2
    for (int dq = 0; dq < 32; ++dq) {
        int nq = (dq + 1) & 31;  // prefetch next (wrap harmless)
        #pragma unroll
        for (int bi = 0; bi < 8; ++bi) xn[bi] = __ldg(&xr[bi][nq]);
        #pragma unroll
        for (int dd = 0; dd < 4; ++dd) {
            unsigned long long a01, a23, b01, b23;
            unsigned rowoff = (unsigned)(dq * 4 + dd) * 256u;
            asm volatile("ld.shared.v2.b64 {%0,%1},[%2];" : "=l"(a01), "=l"(a23) : "r"(wA + rowoff));
            asm volatile("ld.shared.v2.b64 {%0,%1},[%2];" : "=l"(b01), "=l"(b23) : "r"(wB + rowoff));
            #pragma unroll
            for (int bi = 0; bi < 8; ++bi) {
                float xs = (dd == 0) ? xv[bi].x : (dd == 1) ? xv[bi].y
                         : (dd == 2) ? xv[bi].z : xv[bi].w;
                unsigned long long xb;
                asm("mov.b64 %0, {%1,%1};" : "=l"(xb) : "f"(xs));
                asm("fma.rn.f32x2 %0, %1, %2, %0;" : "+l"(acc[bi][0]) : "l"(xb), "l"(a01));
                asm("fma.rn.f32x2 %0, %1, %2, %0;" : "+l"(acc[bi][1]) : "l"(xb), "l"(a23));
                asm("fma.rn.f32x2 %0, %1, %2, %0;" : "+l"(acc[bi][2]) : "l"(xb), "l"(b01));
                asm("fma.rn.f32x2 %0, %1, %2, %0;" : "+l"(acc[bi][3]) : "l"(xb), "l"(b23));
            }
        }
        #pragma unroll
        for (int bi = 0; bi < 8; ++bi) xv[bi] = xn[bi];
    }
    #pragma unroll
    for (int bi = 0; bi < 8; ++bi) {
        float4 o0, o1;
        asm("mov.b64 {%0,%1}, %2;" : "=f"(o0.x), "=f"(o0.y) : "l"(acc[bi][0]));
        asm("mov.b64 {%0,%1}, %2;" : "=f"(o0.z), "=f"(o0.w) : "l"(acc[bi][1]));
        asm("mov.b64 {%0,%1}, %2;" : "=f"(o1.x), "=f"(o1.y) : "l"(acc[bi][2]));
        asm("mov.b64 {%0,%1}, %2;" : "=f"(o1.z), "=f"(o1.w) : "l"(acc[bi][3]));
        float* dst = g_priors + ((size_t)(n * B_ + b0 + bi) * M_ + m) * T_;
        *reinterpret_cast<float4*>(dst + 4 * tx) = o0;
        *reinterpret_cast<float4*>(dst + 32 + 4 * tx) = o1;
    }
}

// ---------------------------------------------------------------------------
// K3: per (b,n) block (128 threads): votes GEMM (8m x 8l f32x2 tiles,
//     pv prefetched one tq ahead) + sigmoid, mean-over-M, dispersion, relu,
//     softmax over M, next_caps, LN. lh staged [t][128]; votes overwrite it
//     (stride 132) after the GEMM. Dynamic smem 52480 B.
// ---------------------------------------------------------------------------
__global__ __launch_bounds__(128, 3) void k_route(
    const float* __restrict__ thr, const float* __restrict__ gamma,
    const float* __restrict__ beta, float* __restrict__ out)
{
    extern __shared__ float smd[];
    float* lhT  = smd;                 // GEMM: [64 t][128 l]; after: votes [64 m][132]
    float* ps   = lhT + M_ * 132;      // [64 m][68]
    float* vbar = ps + M_ * 68;        // 128
    float* wgt  = vbar + L_;           // 64
    float* prob = wgt + M_;            // 64
    float* ncs  = prob + M_;           // 64

    int tid = threadIdx.x;
    int b = blockIdx.x & 255;          // B_ = 256
    int n = blockIdx.x >> 8;

    {   // lh: 8192 floats, contiguous, float4
        const float4* s4 = reinterpret_cast<const float4*>(g_lh);
        float4* d4 = reinterpret_cast<float4*>(lhT);
        for (int i = tid; i < (T_ * L_) / 4; i += 128) d4[i] = s4[i];
    }
    {   // ps: 4096 floats, src contiguous, dst stride 68 (float4-aligned)
        const float4* s4 = reinterpret_cast<const float4*>(
            g_priors + ((size_t)(n * B_ + b) * M_) * T_);
        for (int i = tid; i < M_ * (T_ / 4); i += 128) {
            int r = i >> 4, c = i & 15;
            reinterpret_cast<float4*>(ps + r * 68)[c] = s4[i];
        }
    }
    __syncthreads();

    unsigned lhb = (unsigned)__cvta_generic_to_shared(lhT);
    unsigned psb = (unsigned)__cvta_generic_to_shared(ps);
    int lx = tid & 15;                 // l quads: 4lx..+3, 64+4lx..+3
    int my = tid >> 4;                 // m = my*8 .. +7
    unsigned hA = lhb + (unsigned)lx * 16u;        // quad A
    unsigned hB = hA + 256u;                       // quad B (l+64)
    unsigned prow = psb + (unsigned)my * 2176u;    // my*8 rows * 272B

    unsigned long long acc[8][4];
    #pragma unroll
    for (int i = 0; i < 8; ++i)
        #pragma unroll
        for (int j = 0; j < 4; ++j) acc[i][j] = 0ull;

    float4 pv[8], pn[8];
    #pragma unroll
    for (int i = 0; i < 8; ++i)
        asm volatile("ld.shared.v4.f32 {%0,%1,%2,%3},[%4];"
                     : "=f"(pv[i].x), "=f"(pv[i].y), "=f"(pv[i].z), "=f"(pv[i].w)
                     : "r"(prow + (unsigned)i * 272u));

    #pragma unroll 2
    for (int tq = 0; tq < 16; ++tq) {  // t = 4tq .. 4tq+3
        unsigned ntq = (unsigned)((tq + 1) & 15);  // prefetch next (wrap harmless)
        #pragma unroll
        for (int i = 0; i < 8; ++i)
            asm volatile("ld.shared.v4.f32 {%0,%1,%2,%3},[%4];"
                         : "=f"(pn[i].x), "=f"(pn[i].y), "=f"(pn[i].z), "=f"(pn[i].w)
                         : "r"(prow + (unsigned)i * 272u + ntq * 16u));
        #pragma unroll
        for (int dd = 0; dd < 4; ++dd) {
            unsigned long long ha0, ha1, hb0, hb1;
            unsigned rowoff = (unsigned)(tq * 4 + dd) * 512u;
            asm volatile("ld.shared.v2.b64 {%0,%1},[%2];" : "=l"(ha0), "=l"(ha1) : "r"(hA + rowoff));
            asm volatile("ld.shared.v2.b64 {%0,%1},[%2];" : "=l"(hb0), "=l"(hb1) : "r"(hB + rowoff));
            #pragma unroll
            for (int i = 0; i < 8; ++i) {
                float xs = (dd == 0) ? pv[i].x : (dd == 1) ? pv[i].y
                         : (dd == 2) ? pv[i].z : pv[i].w;
                unsigned long long pa;
                asm("mov.b64 %0, {%1,%1};" : "=l"(pa) : "f"(xs));
                asm("fma.rn.f32x2 %0, %1, %2, %0;" : "+l"(acc[i][0]) : "l"(pa), "l"(ha0));
                asm("fma.rn.f32x2 %0, %1, %2, %0;" : "+l"(acc[i][1]) : "l"(pa), "l"(ha1));
                asm("fma.rn.f32x2 %0, %1, %2, %0;" : "+l"(acc[i][2]) : "l"(pa), "l"(hb0));
                asm("fma.rn.f32x2 %0, %1, %2, %0;" : "+l"(acc[i][3]) : "l"(pa), "l"(hb1));
            }
        }
        #pragma unroll
        for (int i = 0; i < 8; ++i) pv[i] = pn[i];
    }
    __syncthreads();  // all lhT reads done -> region dead, reuse as votes [m][132]

    // sigmoid + store votes: acc[i][j] -> m = 8my+i, l = (j>=2)*64 + 4lx + (j&1)*2
    #pragma unroll
    for (int i = 0; i < 8; ++i) {
        int m = my * 8 + i;
        #pragma unroll
        for (int j = 0; j < 4; ++j) {
            float v0, v1;
            asm("mov.b64 {%0,%1}, %2;" : "=f"(v0), "=f"(v1) : "l"(acc[i][j]));
            v0 = 1.0f / (1.0f + __expf(-v0));
            v1 = 1.0f / (1.0f + __expf(-v1));
            int l = ((j >> 1) << 6) + 4 * lx + ((j & 1) << 1);
            unsigned a = lhb + (unsigned)(m * 132 + l) * 4u;
            asm volatile("st.shared.v2.f32 [%0],{%1,%2};" :: "r"(a), "f"(v0), "f"(v1) : "memory");
        }
    }
    __syncthreads();
    float* vt = lhT;  // [m][132]

    // vbar[l] = mean over m  (lane-contiguous columns: conflict-free)
    {
        float s = 0.f;
        #pragma unroll 8
        for (int m = 0; m < M_; ++m) s += vt[m * 132 + tid];
        vbar[tid] = s * (1.0f / M_);
    }
    __syncthreads();

    // dispersion + relu(thread^2 - dis): 4 threads per m, 2 reps (128 thr).
    // banks (m*132 + 4k + q) % 32 = (4m + 4k + q) % 32 -> all 32 distinct.
    #pragma unroll 1
    for (int rep = 0; rep < 2; ++rep) {
        int m = rep * 32 + (tid >> 2), q = tid & 3;
        float s = 0.f;
        #pragma unroll 8
        for (int k = 0; k < 32; ++k) {
            int l = 4 * k + q;
            float dv = vt[m * 132 + l] - vbar[l];
            s = fmaf(dv, dv, s);
        }
        s += __shfl_xor_sync(0xffffffffu, s, 1);
        s += __shfl_xor_sync(0xffffffffu, s, 2);
        if (q == 0) {
            float tw = thr[m * N_ + n];
            wgt[m] = fmaxf(fmaf(tw, tw, -s * (1.0f / L_)), 0.0f);
        }
    }
    __syncthreads();

    // softmax over M
    if (tid < M_) {
        float mxw = -3.0e38f;
        #pragma unroll 8
        for (int m = 0; m < M_; ++m) mxw = fmaxf(mxw, wgt[m]);
        prob[tid] = __expf(wgt[tid] - mxw);
    }
    __syncthreads();

    // next_caps
    if (tid < T_) {
        float psum = 0.f;
        #pragma unroll 8
        for (int m = 0; m < M_; ++m) psum += prob[m];
        float nc = 0.f;
        #pragma unroll 8
        for (int m = 0; m < M_; ++m) nc = fmaf(prob[m], ps[m * 68 + tid], nc);
        ncs[tid] = nc / psum;
    }
    __syncthreads();

    // layernorm over T
    if (tid < T_) {
        float mu = 0.f;
        #pragma unroll 8
        for (int t2 = 0; t2 < T_; ++t2) mu += ncs[t2];
        mu *= (1.0f / T_);
        float var = 0.f;
        #pragma unroll 8
        for (int t2 = 0; t2 < T_; ++t2) { float dv = ncs[t2] - mu; var = fmaf(dv, dv, var); }
        var *= (1.0f / T_);
        float y = (ncs[tid] - mu) * rsqrtf(var + 1e-5f) * gamma[tid] + beta[tid];
        out[((size_t)b * N_ + n) * T_ + tid] = y;
    }
}

// ---------------------------------------------------------------------------
// Launch
// ---------------------------------------------------------------------------
extern "C" void kernel_launch(void* const* d_in, const int* in_sizes, int n_in,
                              void* d_out, int out_size) {
    const float* x      = (const float*)d_in[0];
    const float* rw     = (const float*)d_in[1];
    const float* thr    = (const float*)d_in[2];
    const float* leaves = (const float*)d_in[3];
    const float* gamma  = (const float*)d_in[4];
    const float* beta   = (const float*)d_in[5];
    float* out = (float*)d_out;

    k_leaves<<<1, 128>>>(leaves);
    k_entmax<<<M_ * N_, 128>>>(rw);
    k_priors<<<M_ * N_ * 2, 128>>>(x);

    const int smem_route = (M_ * 132 + M_ * 68 + L_ + 3 * M_) * 4;  // 52480 B
    static int attr_set = 0;
    if (!attr_set) {
        cudaFuncSetAttribute(k_route, cudaFuncAttributeMaxDynamicSharedMemorySize, smem_route);
        attr_set = 1;
    }
    k_route<<<B_ * N_, 128, smem_route>>>(thr, gamma, beta, out);
}

// round 10
// speedup vs baseline: 1.0664x; 1.0664x over previous
#include <cuda_runtime.h>
#include <math.h>

#define B_ 256
#define M_ 64
#define N_ 32
#define D_ 128
#define T_ 64
#define L_ 128

// Scratch (allocation-free: __device__ globals)
__device__ float g_WT[(size_t)M_ * N_ * D_ * T_];      // entmax weights, [mn][d][t]
__device__ float g_priors[(size_t)N_ * B_ * M_ * T_];  // priors, [n][b][m][t]
__device__ float g_lh[T_ * L_];                        // normalized leaves, TRANSPOSED [t][l]

// ---------------------------------------------------------------------------
// K0: normalize routing_leaves rows; store transposed [t][l]
// ---------------------------------------------------------------------------
__global__ void k_leaves(const float* __restrict__ leaves) {
    int l = threadIdx.x;
    if (l < L_) {
        float s = 0.f;
        #pragma unroll
        for (int t = 0; t < T_; ++t) { float v = leaves[l * T_ + t]; s = fmaf(v, v, s); }
        float inv = 1.0f / fmaxf(sqrtf(s), 1e-12f);
        #pragma unroll
        for (int t = 0; t < T_; ++t) g_lh[t * L_ + l] = leaves[l * T_ + t] * inv;
    }
}

// ---------------------------------------------------------------------------
// K1: exact 1.5-entmax over D per (m,n,t) column via 12 bisection + 2 Newton
//     on f(tau) = sum max(z - tau, 0)^2 = 1. 2 threads/column.
//     Output layout: g_WT[mn][d][t].
// ---------------------------------------------------------------------------
__global__ __launch_bounds__(128) void k_entmax(const float* __restrict__ rw) {
    __shared__ float sm[D_ * 65];  // [d][t] pad 65
    int mn = blockIdx.x;
    const float* src = rw + (size_t)mn * D_ * T_;
    for (int i = threadIdx.x; i < D_ * T_; i += 128)
        sm[(i >> 6) * 65 + (i & 63)] = src[i];
    __syncthreads();

    int col = threadIdx.x >> 1, half = threadIdx.x & 1;
    float z[64];
    float mx = -3.0e38f;
    #pragma unroll
    for (int k = 0; k < 64; ++k) {
        z[k] = sm[(half * 64 + k) * 65 + col];
        mx = fmaxf(mx, z[k]);
    }
    mx = fmaxf(mx, __shfl_xor_sync(0xffffffffu, mx, 1));
    #pragma unroll
    for (int k = 0; k < 64; ++k) z[k] = 0.5f * z[k] - 0.5f * mx;

    float lo = -1.0f, hi = 0.0f;
    #pragma unroll 1
    for (int it = 0; it < 12; ++it) {
        float mid = 0.5f * (lo + hi);
        float s0 = 0.f, s1 = 0.f, s2 = 0.f, s3 = 0.f;
        #pragma unroll
        for (int k = 0; k < 64; k += 4) {
            float a0 = fmaxf(z[k + 0] - mid, 0.f); s0 = fmaf(a0, a0, s0);
            float a1 = fmaxf(z[k + 1] - mid, 0.f); s1 = fmaf(a1, a1, s1);
            float a2 = fmaxf(z[k + 2] - mid, 0.f); s2 = fmaf(a2, a2, s2);
            float a3 = fmaxf(z[k + 3] - mid, 0.f); s3 = fmaf(a3, a3, s3);
        }
        float s = (s0 + s1) + (s2 + s3);
        s += __shfl_xor_sync(0xffffffffu, s, 1);
        if (s >= 1.0f) lo = mid; else hi = mid;
    }
    float tau = 0.5f * (lo + hi);
    #pragma unroll 1
    for (int it = 0; it < 2; ++it) {
        float f0 = 0.f, f1 = 0.f, g0 = 0.f, g1 = 0.f;
        #pragma unroll
        for (int k = 0; k < 64; k += 2) {
            float a0 = fmaxf(z[k + 0] - tau, 0.f); f0 = fmaf(a0, a0, f0); g0 += a0;
            float a1 = fmaxf(z[k + 1] - tau, 0.f); f1 = fmaf(a1, a1, f1); g1 += a1;
        }
        float f = f0 + f1, g = g0 + g1;
        f += __shfl_xor_sync(0xffffffffu, f, 1);
        g += __shfl_xor_sync(0xffffffffu, g, 1);
        tau += (f - 1.0f) / fmaxf(2.0f * g, 1e-12f);
    }

    #pragma unroll
    for (int k = 0; k < 64; ++k) {
        float a = fmaxf(z[k] - tau, 0.f);
        sm[(half * 64 + k) * 65 + col] = a * a;
    }
    __syncthreads();
    float* dst = g_WT + (size_t)mn * D_ * T_;  // [d][t]
    for (int i = threadIdx.x; i < D_ * T_; i += 128)
        dst[i] = sm[(i >> 6) * 65 + (i & 63)];
}

// ---------------------------------------------------------------------------
// K2: priors[b,m,n,t] = sum_d x[b,m,d] * W[m,n,d,t].
//     Grid = 2 * M_*N_: blockIdx = mn*2 + chunk (128 b's per block).
//     128 threads, tile 8 b x 8 t (t quads 4tx..+3, 32+4tx..+3).
//     Single x base pointer + compile-time row offsets (low reg pressure).
//     W staged [d][64] in smem. Packed fma.rn.f32x2. Output [n][b][m][t].
// ---------------------------------------------------------------------------
__global__ __launch_bounds__(128, 4) void k_priors(const float* __restrict__ x) {
    __shared__ __align__(16) float ws[D_ * 64];  // [d][t], rows 256B
    int mn = blockIdx.x >> 1;
    int chunk = blockIdx.x & 1;
    int m = mn >> 5, n = mn & 31;
    {
        const float4* wsrc = reinterpret_cast<const float4*>(g_WT + (size_t)mn * D_ * T_);
        float4* wd = reinterpret_cast<float4*>(ws);
        for (int i = threadIdx.x; i < D_ * T_ / 4; i += 128) wd[i] = wsrc[i];
    }
    __syncthreads();
    unsigned wsb = (unsigned)__cvta_generic_to_shared(ws);
    int tx = threadIdx.x & 7;    // t quads: 4tx..+3 and 32+4tx..+3
    int by = threadIdx.x >> 3;   // b-group (0..15), 8 b's each
    unsigned wA = wsb + (unsigned)tx * 16u;  // quad A
    unsigned wB = wA + 128u;                 // quad B (t+32)

    int b0 = chunk * 128 + by * 8;
    unsigned long long acc[8][4];
    #pragma unroll
    for (int bi = 0; bi < 8; ++bi)
        #pragma unroll
        for (int j = 0; j < 4; ++j) acc[bi][j] = 0ull;

    // single base pointer; row bi at compile-time offset bi*(M_*D_/4) float4s
    const float4* xb = reinterpret_cast<const float4*>(x + ((size_t)b0 * M_ + m) * D_);

    #pragma unroll 2
    for (int dq = 0; dq < 32; ++dq) {
        float4 xv[8];
        #pragma unroll
        for (int bi = 0; bi < 8; ++bi) xv[bi] = __ldg(xb + bi * (M_ * D_ / 4) + dq);
        #pragma unroll
        for (int dd = 0; dd < 4; ++dd) {
            unsigned long long a01, a23, b01, b23;
            unsigned rowoff = (unsigned)(dq * 4 + dd) * 256u;
            asm volatile("ld.shared.v2.b64 {%0,%1},[%2];" : "=l"(a01), "=l"(a23) : "r"(wA + rowoff));
            asm volatile("ld.shared.v2.b64 {%0,%1},[%2];" : "=l"(b01), "=l"(b23) : "r"(wB + rowoff));
            #pragma unroll
            for (int bi = 0; bi < 8; ++bi) {
                float xs = (dd == 0) ? xv[bi].x : (dd == 1) ? xv[bi].y
                         : (dd == 2) ? xv[bi].z : xv[bi].w;
                unsigned long long xp;
                asm("mov.b64 %0, {%1,%1};" : "=l"(xp) : "f"(xs));
                asm("fma.rn.f32x2 %0, %1, %2, %0;" : "+l"(acc[bi][0]) : "l"(xp), "l"(a01));
                asm("fma.rn.f32x2 %0, %1, %2, %0;" : "+l"(acc[bi][1]) : "l"(xp), "l"(a23));
                asm("fma.rn.f32x2 %0, %1, %2, %0;" : "+l"(acc[bi][2]) : "l"(xp), "l"(b01));
                asm("fma.rn.f32x2 %0, %1, %2, %0;" : "+l"(acc[bi][3]) : "l"(xp), "l"(b23));
            }
        }
    }
    float* dst0 = g_priors + ((size_t)(n * B_ + b0) * M_ + m) * T_;
    #pragma unroll
    for (int bi = 0; bi < 8; ++bi) {
        float4 o0, o1;
        asm("mov.b64 {%0,%1}, %2;" : "=f"(o0.x), "=f"(o0.y) : "l"(acc[bi][0]));
        asm("mov.b64 {%0,%1}, %2;" : "=f"(o0.z), "=f"(o0.w) : "l"(acc[bi][1]));
        asm("mov.b64 {%0,%1}, %2;" : "=f"(o1.x), "=f"(o1.y) : "l"(acc[bi][2]));
        asm("mov.b64 {%0,%1}, %2;" : "=f"(o1.z), "=f"(o1.w) : "l"(acc[bi][3]));
        float* dst = dst0 + (size_t)bi * M_ * T_;
        *reinterpret_cast<float4*>(dst + 4 * tx) = o0;
        *reinterpret_cast<float4*>(dst + 32 + 4 * tx) = o1;
    }
}

// ---------------------------------------------------------------------------
// K3: per (b,n) block (128 threads): votes GEMM (8m x 8l f32x2 tiles).
//     Votes stay in REGISTERS: sigmoid in place, vbar via an 8x132 partial-sum
//     table (aliased into dead lhT), dispersion from regs + 16-lane shfl
//     reduce. Then softmax over M, next_caps, LN.
//     Dynamic smem: lhT [64][128] + ps [64][68] = 50176 B -> 4 blocks/SM.
// ---------------------------------------------------------------------------
__global__ __launch_bounds__(128, 4) void k_route(
    const float* __restrict__ thr, const float* __restrict__ gamma,
    const float* __restrict__ beta, float* __restrict__ out)
{
    extern __shared__ float smd[];
    float* lhT  = smd;                 // GEMM: [64 t][128 l]; dead after GEMM
    float* ps   = lhT + T_ * L_;       // [64 m][68]
    // aliases into dead lhT region:
    float* psum = lhT;                 // [8][132] partial sums for vbar
    float* vbar = lhT + 8 * 132;       // 128
    float* wgt  = vbar + L_;           // 64
    float* prob = wgt + M_;            // 64
    float* ncs  = prob + M_;           // 64

    int tid = threadIdx.x;
    int b = blockIdx.x & 255;          // B_ = 256
    int n = blockIdx.x >> 8;

    {   // lh: 8192 floats, contiguous, float4
        const float4* s4 = reinterpret_cast<const float4*>(g_lh);
        float4* d4 = reinterpret_cast<float4*>(lhT);
        for (int i = tid; i < (T_ * L_) / 4; i += 128) d4[i] = s4[i];
    }
    {   // ps: 4096 floats, src contiguous, dst stride 68 (float4-aligned)
        const float4* s4 = reinterpret_cast<const float4*>(
            g_priors + ((size_t)(n * B_ + b) * M_) * T_);
        for (int i = tid; i < M_ * (T_ / 4); i += 128) {
            int r = i >> 4, c = i & 15;
            reinterpret_cast<float4*>(ps + r * 68)[c] = s4[i];
        }
    }
    __syncthreads();

    unsigned lhb = (unsigned)__cvta_generic_to_shared(lhT);
    unsigned psb = (unsigned)__cvta_generic_to_shared(ps);
    int lx = tid & 15;                 // l quads: 4lx..+3, 64+4lx..+3
    int my = tid >> 4;                 // m = my*8 .. +7
    unsigned hA = lhb + (unsigned)lx * 16u;        // quad A
    unsigned hB = hA + 256u;                       // quad B (l+64)
    unsigned prow = psb + (unsigned)my * 2176u;    // my*8 rows * 272B

    unsigned long long acc[8][4];
    #pragma unroll
    for (int i = 0; i < 8; ++i)
        #pragma unroll
        for (int j = 0; j < 4; ++j) acc[i][j] = 0ull;

    #pragma unroll 2
    for (int tq = 0; tq < 16; ++tq) {  // t = 4tq .. 4tq+3
        float4 pv[8];
        #pragma unroll
        for (int i = 0; i < 8; ++i)
            asm volatile("ld.shared.v4.f32 {%0,%1,%2,%3},[%4];"
                         : "=f"(pv[i].x), "=f"(pv[i].y), "=f"(pv[i].z), "=f"(pv[i].w)
                         : "r"(prow + (unsigned)i * 272u + (unsigned)tq * 16u));
        #pragma unroll
        for (int dd = 0; dd < 4; ++dd) {
            unsigned long long ha0, ha1, hb0, hb1;
            unsigned rowoff = (unsigned)(tq * 4 + dd) * 512u;
            asm volatile("ld.shared.v2.b64 {%0,%1},[%2];" : "=l"(ha0), "=l"(ha1) : "r"(hA + rowoff));
            asm volatile("ld.shared.v2.b64 {%0,%1},[%2];" : "=l"(hb0), "=l"(hb1) : "r"(hB + rowoff));
            #pragma unroll
            for (int i = 0; i < 8; ++i) {
                float xs = (dd == 0) ? pv[i].x : (dd == 1) ? pv[i].y
                         : (dd == 2) ? pv[i].z : pv[i].w;
                unsigned long long pa;
                asm("mov.b64 %0, {%1,%1};" : "=l"(pa) : "f"(xs));
                asm("fma.rn.f32x2 %0, %1, %2, %0;" : "+l"(acc[i][0]) : "l"(pa), "l"(ha0));
                asm("fma.rn.f32x2 %0, %1, %2, %0;" : "+l"(acc[i][1]) : "l"(pa), "l"(ha1));
                asm("fma.rn.f32x2 %0, %1, %2, %0;" : "+l"(acc[i][2]) : "l"(pa), "l"(hb0));
                asm("fma.rn.f32x2 %0, %1, %2, %0;" : "+l"(acc[i][3]) : "l"(pa), "l"(hb1));
            }
        }
    }
    __syncthreads();  // all lhT reads done -> region dead (psum/vbar/... alias)

    // sigmoid in place (votes stay in registers, repacked into acc)
    #pragma unroll
    for (int i = 0; i < 8; ++i)
        #pragma unroll
        for (int j = 0; j < 4; ++j) {
            float v0, v1;
            asm("mov.b64 {%0,%1}, %2;" : "=f"(v0), "=f"(v1) : "l"(acc[i][j]));
            v0 = 1.0f / (1.0f + __expf(-v0));
            v1 = 1.0f / (1.0f + __expf(-v1));
            asm("mov.b64 %0, {%1,%2};" : "=l"(acc[i][j]) : "f"(v0), "f"(v1));
        }

    // partial sums over this thread's 8 m's for its 8 l's -> psum[my][l]
    {
        float sA[4] = {0.f, 0.f, 0.f, 0.f};   // l = 4lx + 0..3
        float sB[4] = {0.f, 0.f, 0.f, 0.f};   // l = 64 + 4lx + 0..3
        #pragma unroll
        for (int i = 0; i < 8; ++i) {
            float v0, v1;
            asm("mov.b64 {%0,%1}, %2;" : "=f"(v0), "=f"(v1) : "l"(acc[i][0]));
            sA[0] += v0; sA[1] += v1;
            asm("mov.b64 {%0,%1}, %2;" : "=f"(v0), "=f"(v1) : "l"(acc[i][1]));
            sA[2] += v0; sA[3] += v1;
            asm("mov.b64 {%0,%1}, %2;" : "=f"(v0), "=f"(v1) : "l"(acc[i][2]));
            sB[0] += v0; sB[1] += v1;
            asm("mov.b64 {%0,%1}, %2;" : "=f"(v0), "=f"(v1) : "l"(acc[i][3]));
            sB[2] += v0; sB[3] += v1;
        }
        float4* rowA = reinterpret_cast<float4*>(psum + my * 132 + 4 * lx);
        float4* rowB = reinterpret_cast<float4*>(psum + my * 132 + 64 + 4 * lx);
        *rowA = make_float4(sA[0], sA[1], sA[2], sA[3]);
        *rowB = make_float4(sB[0], sB[1], sB[2], sB[3]);
    }
    __syncthreads();

    // vbar[l] = (sum over 8 my-rows) / 64
    if (tid < L_) {
        float s = 0.f;
        #pragma unroll
        for (int r = 0; r < 8; ++r) s += psum[r * 132 + tid];
        vbar[tid] = s * (1.0f / M_);
    }
    __syncthreads();

    // dispersion from registers: per i, sum over this thread's 8 l's of
    // (v - vbar)^2, then shfl-reduce over the 16 lx lanes.
    {
        float4 vbA = *reinterpret_cast<const float4*>(vbar + 4 * lx);
        float4 vbB = *reinterpret_cast<const float4*>(vbar + 64 + 4 * lx);
        float dis[8];
        #pragma unroll
        for (int i = 0; i < 8; ++i) {
            float v0, v1, s = 0.f, d;
            asm("mov.b64 {%0,%1}, %2;" : "=f"(v0), "=f"(v1) : "l"(acc[i][0]));
            d = v0 - vbA.x; s = fmaf(d, d, s);
            d = v1 - vbA.y; s = fmaf(d, d, s);
            asm("mov.b64 {%0,%1}, %2;" : "=f"(v0), "=f"(v1) : "l"(acc[i][1]));
            d = v0 - vbA.z; s = fmaf(d, d, s);
            d = v1 - vbA.w; s = fmaf(d, d, s);
            asm("mov.b64 {%0,%1}, %2;" : "=f"(v0), "=f"(v1) : "l"(acc[i][2]));
            d = v0 - vbB.x; s = fmaf(d, d, s);
            d = v1 - vbB.y; s = fmaf(d, d, s);
            asm("mov.b64 {%0,%1}, %2;" : "=f"(v0), "=f"(v1) : "l"(acc[i][3]));
            d = v0 - vbB.z; s = fmaf(d, d, s);
            d = v1 - vbB.w; s = fmaf(d, d, s);
            dis[i] = s;
        }
        #pragma unroll
        for (int i = 0; i < 8; ++i) {
            dis[i] += __shfl_xor_sync(0xffffffffu, dis[i], 1);
            dis[i] += __shfl_xor_sync(0xffffffffu, dis[i], 2);
            dis[i] += __shfl_xor_sync(0xffffffffu, dis[i], 4);
            dis[i] += __shfl_xor_sync(0xffffffffu, dis[i], 8);
        }
        if (lx == 0) {
            #pragma unroll
            for (int i = 0; i < 8; ++i) {
                int m = my * 8 + i;
                float tw = thr[m * N_ + n];
                wgt[m] = fmaxf(fmaf(tw, tw, -dis[i] * (1.0f / L_)), 0.0f);
            }
        }
    }
    __syncthreads();

    // softmax over M
    if (tid < M_) {
        float mxw = -3.0e38f;
        #pragma unroll 8
        for (int m = 0; m < M_; ++m) mxw = fmaxf(mxw, wgt[m]);
        prob[tid] = __expf(wgt[tid] - mxw);
    }
    __syncthreads();

    // next_caps
    if (tid < T_) {
        float psumv = 0.f;
        #pragma unroll 8
        for (int m = 0; m < M_; ++m) psumv += prob[m];
        float nc = 0.f;
        #pragma unroll 8
        for (int m = 0; m < M_; ++m) nc = fmaf(prob[m], ps[m * 68 + tid], nc);
        ncs[tid] = nc / psumv;
    }
    __syncthreads();

    // layernorm over T
    if (tid < T_) {
        float mu = 0.f;
        #pragma unroll 8
        for (int t2 = 0; t2 < T_; ++t2) mu += ncs[t2];
        mu *= (1.0f / T_);
        float var = 0.f;
        #pragma unroll 8
        for (int t2 = 0; t2 < T_; ++t2) { float dv = ncs[t2] - mu; var = fmaf(dv, dv, var); }
        var *= (1.0f / T_);
        float y = (ncs[tid] - mu) * rsqrtf(var + 1e-5f) * gamma[tid] + beta[tid];
        out[((size_t)b * N_ + n) * T_ + tid] = y;
    }
}

// ---------------------------------------------------------------------------
// Launch
// ---------------------------------------------------------------------------
extern "C" void kernel_launch(void* const* d_in, const int* in_sizes, int n_in,
                              void* d_out, int out_size) {
    const float* x      = (const float*)d_in[0];
    const float* rw     = (const float*)d_in[1];
    const float* thr    = (const float*)d_in[2];
    const float* leaves = (const float*)d_in[3];
    const float* gamma  = (const float*)d_in[4];
    const float* beta   = (const float*)d_in[5];
    float* out = (float*)d_out;

    k_leaves<<<1, 128>>>(leaves);
    k_entmax<<<M_ * N_, 128>>>(rw);
    k_priors<<<M_ * N_ * 2, 128>>>(x);

    const int smem_route = (T_ * L_ + M_ * 68) * 4;  // 50176 B
    static int attr_set = 0;
    if (!attr_set) {
        cudaFuncSetAttribute(k_route, cudaFuncAttributeMaxDynamicSharedMemorySize, smem_route);
        attr_set = 1;
    }
    k_route<<<B_ * N_, 128, smem_route>>>(thr, gamma, beta, out);
}

// round 13
// speedup vs baseline: 1.1528x; 1.0810x over previous
#include <cuda_runtime.h>
#include <cuda_bf16.h>
#include <cstdint>
#include <math.h>

#define B_ 256
#define M_ 64
#define N_ 32
#define D_ 128
#define T_ 64
#define L_ 128

// Scratch (allocation-free: __device__ globals)
__device__ float g_WT[(size_t)M_ * N_ * D_ * T_];                  // entmax weights, [mn][d][t]
__device__ __nv_bfloat16 g_ph[(size_t)N_ * B_ * M_ * T_];          // priors hi, [n][b][m][t]
__device__ __nv_bfloat16 g_pl[(size_t)N_ * B_ * M_ * T_];          // priors lo
__device__ __nv_bfloat16 g_lhh[L_ * T_];                           // leaves hi, [l][t]
__device__ __nv_bfloat16 g_lhl[L_ * T_];                           // leaves lo

// ---------------------------------------------------------------------------
// K0: normalize routing_leaves rows; emit bf16 hi/lo [l][t]
// ---------------------------------------------------------------------------
__global__ void k_leaves(const float* __restrict__ leaves) {
    int l = threadIdx.x;
    if (l >= L_) return;
    float v[T_];
    float s = 0.f;
    #pragma unroll
    for (int t = 0; t < T_; ++t) { v[t] = leaves[l * T_ + t]; s = fmaf(v[t], v[t], s); }
    float inv = 1.0f / fmaxf(sqrtf(s), 1e-12f);
    #pragma unroll
    for (int t = 0; t < T_; ++t) {
        float f = v[t] * inv;
        __nv_bfloat16 h = __float2bfloat16(f);
        __nv_bfloat16 lo = __float2bfloat16(f - __bfloat162float(h));
        g_lhh[l * T_ + t] = h;
        g_lhl[l * T_ + t] = lo;
    }
}

// ---------------------------------------------------------------------------
// K1: exact 1.5-entmax over D per (m,n,t) column via 12 bisection + 2 Newton
//     on f(tau) = sum max(z - tau, 0)^2 = 1. 2 threads/column. -> g_WT[mn][d][t]
// ---------------------------------------------------------------------------
__global__ __launch_bounds__(128) void k_entmax(const float* __restrict__ rw) {
    __shared__ float sm[D_ * 65];
    int mn = blockIdx.x;
    const float* src = rw + (size_t)mn * D_ * T_;
    for (int i = threadIdx.x; i < D_ * T_; i += 128)
        sm[(i >> 6) * 65 + (i & 63)] = src[i];
    __syncthreads();

    int col = threadIdx.x >> 1, half = threadIdx.x & 1;
    float z[64];
    float mx = -3.0e38f;
    #pragma unroll
    for (int k = 0; k < 64; ++k) {
        z[k] = sm[(half * 64 + k) * 65 + col];
        mx = fmaxf(mx, z[k]);
    }
    mx = fmaxf(mx, __shfl_xor_sync(0xffffffffu, mx, 1));
    #pragma unroll
    for (int k = 0; k < 64; ++k) z[k] = 0.5f * z[k] - 0.5f * mx;

    float lo = -1.0f, hi = 0.0f;
    #pragma unroll 1
    for (int it = 0; it < 12; ++it) {
        float mid = 0.5f * (lo + hi);
        float s0 = 0.f, s1 = 0.f, s2 = 0.f, s3 = 0.f;
        #pragma unroll
        for (int k = 0; k < 64; k += 4) {
            float a0 = fmaxf(z[k + 0] - mid, 0.f); s0 = fmaf(a0, a0, s0);
            float a1 = fmaxf(z[k + 1] - mid, 0.f); s1 = fmaf(a1, a1, s1);
            float a2 = fmaxf(z[k + 2] - mid, 0.f); s2 = fmaf(a2, a2, s2);
            float a3 = fmaxf(z[k + 3] - mid, 0.f); s3 = fmaf(a3, a3, s3);
        }
        float s = (s0 + s1) + (s2 + s3);
        s += __shfl_xor_sync(0xffffffffu, s, 1);
        if (s >= 1.0f) lo = mid; else hi = mid;
    }
    float tau = 0.5f * (lo + hi);
    #pragma unroll 1
    for (int it = 0; it < 2; ++it) {
        float f0 = 0.f, f1 = 0.f, g0 = 0.f, g1 = 0.f;
        #pragma unroll
        for (int k = 0; k < 64; k += 2) {
            float a0 = fmaxf(z[k + 0] - tau, 0.f); f0 = fmaf(a0, a0, f0); g0 += a0;
            float a1 = fmaxf(z[k + 1] - tau, 0.f); f1 = fmaf(a1, a1, f1); g1 += a1;
        }
        float f = f0 + f1, g = g0 + g1;
        f += __shfl_xor_sync(0xffffffffu, f, 1);
        g += __shfl_xor_sync(0xffffffffu, g, 1);
        tau += (f - 1.0f) / fmaxf(2.0f * g, 1e-12f);
    }

    #pragma unroll
    for (int k = 0; k < 64; ++k) {
        float a = fmaxf(z[k] - tau, 0.f);
        sm[(half * 64 + k) * 65 + col] = a * a;
    }
    __syncthreads();
    float* dst = g_WT + (size_t)mn * D_ * T_;
    for (int i = threadIdx.x; i < D_ * T_; i += 128)
        dst[i] = sm[(i >> 6) * 65 + (i & 63)];
}

// ---------------------------------------------------------------------------
// helper: split float4 into packed bf16 hi / lo pairs
// ---------------------------------------------------------------------------
__device__ __forceinline__ uint2 bf16split4(float4 v, uint2* lo) {
    __nv_bfloat16 h0 = __float2bfloat16(v.x), h1 = __float2bfloat16(v.y);
    __nv_bfloat16 h2 = __float2bfloat16(v.z), h3 = __float2bfloat16(v.w);
    __nv_bfloat16 l0 = __float2bfloat16(v.x - __bfloat162float(h0));
    __nv_bfloat16 l1 = __float2bfloat16(v.y - __bfloat162float(h1));
    __nv_bfloat16 l2 = __float2bfloat16(v.z - __bfloat162float(h2));
    __nv_bfloat16 l3 = __float2bfloat16(v.w - __bfloat162float(h3));
    uint2 hi;
    hi.x = (unsigned)__bfloat16_as_ushort(h0) | ((unsigned)__bfloat16_as_ushort(h1) << 16);
    hi.y = (unsigned)__bfloat16_as_ushort(h2) | ((unsigned)__bfloat16_as_ushort(h3) << 16);
    lo->x = (unsigned)__bfloat16_as_ushort(l0) | ((unsigned)__bfloat16_as_ushort(l1) << 16);
    lo->y = (unsigned)__bfloat16_as_ushort(l2) | ((unsigned)__bfloat16_as_ushort(l3) << 16);
    return hi;
}

// ---------------------------------------------------------------------------
// K2: priors GEMM (proven scalar f32x2 core) -> bf16 hi/lo [n][b][m][t].
//     Grid = 2*M_*N_: blockIdx = mn*2 + chunk (128 b's per block). 8b x 8t tile.
// ---------------------------------------------------------------------------
__global__ __launch_bounds__(128, 4) void k_priors(const float* __restrict__ x) {
    __shared__ __align__(16) float ws[D_ * 64];  // [d][t], rows 256B
    int mn = blockIdx.x >> 1;
    int chunk = blockIdx.x & 1;
    int m = mn >> 5, n = mn & 31;
    {
        const float4* wsrc = reinterpret_cast<const float4*>(g_WT + (size_t)mn * D_ * T_);
        float4* wd = reinterpret_cast<float4*>(ws);
        for (int i = threadIdx.x; i < D_ * T_ / 4; i += 128) wd[i] = wsrc[i];
    }
    __syncthreads();
    unsigned wsb = (unsigned)__cvta_generic_to_shared(ws);
    int tx = threadIdx.x & 7;
    int by = threadIdx.x >> 3;
    unsigned wA = wsb + (unsigned)tx * 16u;
    unsigned wB = wA + 128u;

    int b0 = chunk * 128 + by * 8;
    unsigned long long acc[8][4];
    #pragma unroll
    for (int bi = 0; bi < 8; ++bi)
        #pragma unroll
        for (int j = 0; j < 4; ++j) acc[bi][j] = 0ull;

    const float4* xb = reinterpret_cast<const float4*>(x + ((size_t)b0 * M_ + m) * D_);

    #pragma unroll 2
    for (int dq = 0; dq < 32; ++dq) {
        float4 xv[8];
        #pragma unroll
        for (int bi = 0; bi < 8; ++bi) xv[bi] = __ldg(xb + bi * (M_ * D_ / 4) + dq);
        #pragma unroll
        for (int dd = 0; dd < 4; ++dd) {
            unsigned long long a01, a23, b01, b23;
            unsigned rowoff = (unsigned)(dq * 4 + dd) * 256u;
            asm volatile("ld.shared.v2.b64 {%0,%1},[%2];" : "=l"(a01), "=l"(a23) : "r"(wA + rowoff));
            asm volatile("ld.shared.v2.b64 {%0,%1},[%2];" : "=l"(b01), "=l"(b23) : "r"(wB + rowoff));
            #pragma unroll
            for (int bi = 0; bi < 8; ++bi) {
                float xs = (dd == 0) ? xv[bi].x : (dd == 1) ? xv[bi].y
                         : (dd == 2) ? xv[bi].z : xv[bi].w;
                unsigned long long xp;
                asm("mov.b64 %0, {%1,%1};" : "=l"(xp) : "f"(xs));
                asm("fma.rn.f32x2 %0, %1, %2, %0;" : "+l"(acc[bi][0]) : "l"(xp), "l"(a01));
                asm("fma.rn.f32x2 %0, %1, %2, %0;" : "+l"(acc[bi][1]) : "l"(xp), "l"(a23));
                asm("fma.rn.f32x2 %0, %1, %2, %0;" : "+l"(acc[bi][2]) : "l"(xp), "l"(b01));
                asm("fma.rn.f32x2 %0, %1, %2, %0;" : "+l"(acc[bi][3]) : "l"(xp), "l"(b23));
            }
        }
    }
    #pragma unroll
    for (int bi = 0; bi < 8; ++bi) {
        float4 o0, o1;
        asm("mov.b64 {%0,%1}, %2;" : "=f"(o0.x), "=f"(o0.y) : "l"(acc[bi][0]));
        asm("mov.b64 {%0,%1}, %2;" : "=f"(o0.z), "=f"(o0.w) : "l"(acc[bi][1]));
        asm("mov.b64 {%0,%1}, %2;" : "=f"(o1.x), "=f"(o1.y) : "l"(acc[bi][2]));
        asm("mov.b64 {%0,%1}, %2;" : "=f"(o1.z), "=f"(o1.w) : "l"(acc[bi][3]));
        int b = b0 + bi;
        size_t base = (((size_t)n * B_ + b) * M_ + m) * T_;
        uint2 lo0, lo1;
        uint2 hi0 = bf16split4(o0, &lo0);
        uint2 hi1 = bf16split4(o1, &lo1);
        *(uint2*)(g_ph + base + 4 * tx)      = hi0;
        *(uint2*)(g_ph + base + 32 + 4 * tx) = hi1;
        *(uint2*)(g_pl + base + 4 * tx)      = lo0;
        *(uint2*)(g_pl + base + 32 + 4 * tx) = lo1;
    }
}

// ---------------------------------------------------------------------------
// K3: votes GEMM via mma.sync m16n8k16 bf16 (3 hi/lo passes) + epilogue.
//     One CTA per (b,n): 4 warps, each 16m x 128l. smem images padded to
//     144B rows (ldmatrix conflict-free). Votes alias over the dead B images.
//     smem layout (bytes):
//       0      Ah [64][72]b16  (9216)
//       9216   Al              (9216)
//       18432  Bh [128][72]b16 (18432)   | votes f32 [64][132] alias (33792)
//       36864  Bl              (18432)   |
//       55296  vbar[128] wgt[64] prob[64] ncs[64]
// ---------------------------------------------------------------------------
#define K3_SMEM 56832

__global__ __launch_bounds__(128) void k_route(
    const float* __restrict__ thr, const float* __restrict__ gamma,
    const float* __restrict__ beta, float* __restrict__ out)
{
    extern __shared__ __align__(16) char smc[];
    unsigned abase = (unsigned)__cvta_generic_to_shared(smc);

    float* votes = (float*)(smc + 18432);
    float* vbar  = (float*)(smc + 55296);
    float* wgt   = (float*)(smc + 55808);
    float* prob  = (float*)(smc + 56064);
    float* ncs   = (float*)(smc + 56320);

    int tid = threadIdx.x;
    int lane = tid & 31, wid = tid >> 5;
    int b = blockIdx.x & 255;          // B_ = 256
    int n = blockIdx.x >> 8;

    // stage A (ps hi/lo) and B (lh hi/lo), 128B rows -> 144B padded rows
    {
        size_t pbase = (((size_t)n * B_ + b) * M_) * T_;  // elements
        const uint4* sh = (const uint4*)(g_ph + pbase);
        const uint4* sl = (const uint4*)(g_pl + pbase);
        for (int i = tid; i < 512; i += 128) {           // 64 rows x 8 uint4
            int r = i >> 3, q = i & 7;
            *(uint4*)(smc + r * 144 + q * 16) = sh[i];
            *(uint4*)(smc + 9216 + r * 144 + q * 16) = sl[i];
        }
        const uint4* th = (const uint4*)g_lhh;
        const uint4* tl = (const uint4*)g_lhl;
        for (int i = tid; i < 1024; i += 128) {          // 128 rows x 8 uint4
            int r = i >> 3, q = i & 7;
            *(uint4*)(smc + 18432 + r * 144 + q * 16) = th[i];
            *(uint4*)(smc + 36864 + r * 144 + q * 16) = tl[i];
        }
    }
    __syncthreads();

    // fragment addresses
    int m0 = wid * 16;
    unsigned a_off = (unsigned)((m0 + (lane & 15)) * 144) + ((lane & 16) ? 16u : 0u);
    unsigned b_row = (unsigned)((lane & 7) + ((lane & 16) ? 8 : 0));
    unsigned b_col = (lane & 8) ? 16u : 0u;

    float acc[16][4];
    #pragma unroll
    for (int nt = 0; nt < 16; ++nt)
        #pragma unroll
        for (int q = 0; q < 4; ++q) acc[nt][q] = 0.f;

    // 3 passes: (Ah,Bh), (Ah,Bl), (Al,Bh)
    #pragma unroll 1
    for (int pass = 0; pass < 3; ++pass) {
        unsigned Ab = abase + ((pass == 2) ? 9216u : 0u) + a_off;
        unsigned Bb = abase + 18432u + ((pass == 1) ? 18432u : 0u)
                    + b_row * 144u + b_col;
        #pragma unroll
        for (int ks = 0; ks < 4; ++ks) {
            unsigned ra0, ra1, ra2, ra3;
            asm volatile("ldmatrix.sync.aligned.m8n8.x4.shared.b16 {%0,%1,%2,%3},[%4];"
                         : "=r"(ra0), "=r"(ra1), "=r"(ra2), "=r"(ra3)
                         : "r"(Ab + (unsigned)ks * 32u));
            #pragma unroll
            for (int np = 0; np < 8; ++np) {
                unsigned rb0, rb1, rb2, rb3;
                asm volatile("ldmatrix.sync.aligned.m8n8.x4.shared.b16 {%0,%1,%2,%3},[%4];"
                             : "=r"(rb0), "=r"(rb1), "=r"(rb2), "=r"(rb3)
                             : "r"(Bb + (unsigned)np * 2304u + (unsigned)ks * 32u));
                asm volatile(
                    "mma.sync.aligned.m16n8k16.row.col.f32.bf16.bf16.f32 "
                    "{%0,%1,%2,%3},{%4,%5,%6,%7},{%8,%9},{%0,%1,%2,%3};"
                    : "+f"(acc[2 * np][0]), "+f"(acc[2 * np][1]),
                      "+f"(acc[2 * np][2]), "+f"(acc[2 * np][3])
                    : "r"(ra0), "r"(ra1), "r"(ra2), "r"(ra3), "r"(rb0), "r"(rb1));
                asm volatile(
                    "mma.sync.aligned.m16n8k16.row.col.f32.bf16.bf16.f32 "
                    "{%0,%1,%2,%3},{%4,%5,%6,%7},{%8,%9},{%0,%1,%2,%3};"
                    : "+f"(acc[2 * np + 1][0]), "+f"(acc[2 * np + 1][1]),
                      "+f"(acc[2 * np + 1][2]), "+f"(acc[2 * np + 1][3])
                    : "r"(ra0), "r"(ra1), "r"(ra2), "r"(ra3), "r"(rb2), "r"(rb3));
            }
        }
    }
    __syncthreads();  // B images dead -> votes alias

    // sigmoid + store votes[m][132]
    {
        int r0 = m0 + (lane >> 2);
        int cc = (lane & 3) * 2;
        #pragma unroll
        for (int nt = 0; nt < 16; ++nt) {
            int c = nt * 8 + cc;
            float s0 = 1.0f / (1.0f + __expf(-acc[nt][0]));
            float s1 = 1.0f / (1.0f + __expf(-acc[nt][1]));
            float s2 = 1.0f / (1.0f + __expf(-acc[nt][2]));
            float s3 = 1.0f / (1.0f + __expf(-acc[nt][3]));
            *(float2*)(votes + (size_t)r0 * 132 + c) = make_float2(s0, s1);
            *(float2*)(votes + (size_t)(r0 + 8) * 132 + c) = make_float2(s2, s3);
        }
    }
    __syncthreads();

    // vbar[l] = mean over m
    {
        float s = 0.f;
        #pragma unroll 8
        for (int m = 0; m < M_; ++m) s += votes[m * 132 + tid];
        vbar[tid] = s * (1.0f / M_);
    }
    __syncthreads();

    // dispersion + relu(thread^2 - dis): 4 threads per m, 2 reps
    #pragma unroll 1
    for (int rep = 0; rep < 2; ++rep) {
        int m = rep * 32 + (tid >> 2), q = tid & 3;
        float s = 0.f;
        #pragma unroll 8
        for (int k = 0; k < 32; ++k) {
            int l = 4 * k + q;
            float dv = votes[m * 132 + l] - vbar[l];
            s = fmaf(dv, dv, s);
        }
        s += __shfl_xor_sync(0xffffffffu, s, 1);
        s += __shfl_xor_sync(0xffffffffu, s, 2);
        if (q == 0) {
            float tw = thr[m * N_ + n];
            wgt[m] = fmaxf(fmaf(tw, tw, -s * (1.0f / L_)), 0.0f);
        }
    }
    __syncthreads();

    // softmax over M
    if (tid < M_) {
        float mxw = -3.0e38f;
        #pragma unroll 8
        for (int m = 0; m < M_; ++m) mxw = fmaxf(mxw, wgt[m]);
        prob[tid] = __expf(wgt[tid] - mxw);
    }
    __syncthreads();

    // next_caps (ps fp32 reconstructed from the A images)
    if (tid < T_) {
        const __nv_bfloat16* Ah = (const __nv_bfloat16*)smc;
        const __nv_bfloat16* Al = (const __nv_bfloat16*)(smc + 9216);
        float psum = 0.f;
        #pragma unroll 8
        for (int m = 0; m < M_; ++m) psum += prob[m];
        float nc = 0.f;
        #pragma unroll 4
        for (int m = 0; m < M_; ++m) {
            float p = __bfloat162float(Ah[m * 72 + tid]) + __bfloat162float(Al[m * 72 + tid]);
            nc = fmaf(prob[m], p, nc);
        }
        ncs[tid] = nc / psum;
    }
    __syncthreads();

    // layernorm over T
    if (tid < T_) {
        float mu = 0.f;
        #pragma unroll 8
        for (int t2 = 0; t2 < T_; ++t2) mu += ncs[t2];
        mu *= (1.0f / T_);
        float var = 0.f;
        #pragma unroll 8
        for (int t2 = 0; t2 < T_; ++t2) { float dv = ncs[t2] - mu; var = fmaf(dv, dv, var); }
        var *= (1.0f / T_);
        float y = (ncs[tid] - mu) * rsqrtf(var + 1e-5f) * gamma[tid] + beta[tid];
        out[((size_t)b * N_ + n) * T_ + tid] = y;
    }
}

// ---------------------------------------------------------------------------
// Launch
// ---------------------------------------------------------------------------
extern "C" void kernel_launch(void* const* d_in, const int* in_sizes, int n_in,
                              void* d_out, int out_size) {
    const float* x      = (const float*)d_in[0];
    const float* rw     = (const float*)d_in[1];
    const float* thr    = (const float*)d_in[2];
    const float* leaves = (const float*)d_in[3];
    const float* gamma  = (const float*)d_in[4];
    const float* beta   = (const float*)d_in[5];
    float* out = (float*)d_out;

    k_leaves<<<1, 128>>>(leaves);
    k_entmax<<<M_ * N_, 128>>>(rw);
    k_priors<<<M_ * N_ * 2, 128>>>(x);

    static int attr_set = 0;
    if (!attr_set) {
        cudaFuncSetAttribute(k_route, cudaFuncAttributeMaxDynamicSharedMemorySize, K3_SMEM);
        attr_set = 1;
    }
    k_route<<<B_ * N_, 128, K3_SMEM>>>(thr, gamma, beta, out);
}

// round 14
// speedup vs baseline: 1.2423x; 1.0776x over previous
#include <cuda_runtime.h>
#include <cuda_bf16.h>
#include <cstdint>
#include <math.h>

#define B_ 256
#define M_ 64
#define N_ 32
#define D_ 128
#define T_ 64
#define L_ 128

// Scratch (allocation-free: __device__ globals)
__device__ float g_WT[(size_t)M_ * N_ * D_ * T_];                  // entmax weights, [mn][d][t]
__device__ __nv_bfloat16 g_ph[(size_t)N_ * B_ * M_ * T_];          // priors hi, [n][b][m][t]
__device__ __nv_bfloat16 g_pl[(size_t)N_ * B_ * M_ * T_];          // priors lo
__device__ __nv_bfloat16 g_lhh[L_ * T_];                           // leaves hi, [l][t]
__device__ __nv_bfloat16 g_lhl[L_ * T_];                           // leaves lo

// ---------------------------------------------------------------------------
// K0: normalize routing_leaves rows; emit bf16 hi/lo [l][t]
// ---------------------------------------------------------------------------
__global__ void k_leaves(const float* __restrict__ leaves) {
    int l = threadIdx.x;
    if (l >= L_) return;
    float v[T_];
    float s = 0.f;
    #pragma unroll
    for (int t = 0; t < T_; ++t) { v[t] = leaves[l * T_ + t]; s = fmaf(v[t], v[t], s); }
    float inv = 1.0f / fmaxf(sqrtf(s), 1e-12f);
    #pragma unroll
    for (int t = 0; t < T_; ++t) {
        float f = v[t] * inv;
        __nv_bfloat16 h = __float2bfloat16(f);
        __nv_bfloat16 lo = __float2bfloat16(f - __bfloat162float(h));
        g_lhh[l * T_ + t] = h;
        g_lhl[l * T_ + t] = lo;
    }
}

// ---------------------------------------------------------------------------
// K1: exact 1.5-entmax over D per (m,n,t) column via 12 bisection + 2 Newton
//     on f(tau) = sum max(z - tau, 0)^2 = 1. 2 threads/column. -> g_WT[mn][d][t]
// ---------------------------------------------------------------------------
__global__ __launch_bounds__(128) void k_entmax(const float* __restrict__ rw) {
    __shared__ float sm[D_ * 65];
    int mn = blockIdx.x;
    const float* src = rw + (size_t)mn * D_ * T_;
    for (int i = threadIdx.x; i < D_ * T_; i += 128)
        sm[(i >> 6) * 65 + (i & 63)] = src[i];
    __syncthreads();

    int col = threadIdx.x >> 1, half = threadIdx.x & 1;
    float z[64];
    float mx = -3.0e38f;
    #pragma unroll
    for (int k = 0; k < 64; ++k) {
        z[k] = sm[(half * 64 + k) * 65 + col];
        mx = fmaxf(mx, z[k]);
    }
    mx = fmaxf(mx, __shfl_xor_sync(0xffffffffu, mx, 1));
    #pragma unroll
    for (int k = 0; k < 64; ++k) z[k] = 0.5f * z[k] - 0.5f * mx;

    float lo = -1.0f, hi = 0.0f;
    #pragma unroll 1
    for (int it = 0; it < 12; ++it) {
        float mid = 0.5f * (lo + hi);
        float s0 = 0.f, s1 = 0.f, s2 = 0.f, s3 = 0.f;
        #pragma unroll
        for (int k = 0; k < 64; k += 4) {
            float a0 = fmaxf(z[k + 0] - mid, 0.f); s0 = fmaf(a0, a0, s0);
            float a1 = fmaxf(z[k + 1] - mid, 0.f); s1 = fmaf(a1, a1, s1);
            float a2 = fmaxf(z[k + 2] - mid, 0.f); s2 = fmaf(a2, a2, s2);
            float a3 = fmaxf(z[k + 3] - mid, 0.f); s3 = fmaf(a3, a3, s3);
        }
        float s = (s0 + s1) + (s2 + s3);
        s += __shfl_xor_sync(0xffffffffu, s, 1);
        if (s >= 1.0f) lo = mid; else hi = mid;
    }
    float tau = 0.5f * (lo + hi);
    #pragma unroll 1
    for (int it = 0; it < 2; ++it) {
        float f0 = 0.f, f1 = 0.f, g0 = 0.f, g1 = 0.f;
        #pragma unroll
        for (int k = 0; k < 64; k += 2) {
            float a0 = fmaxf(z[k + 0] - tau, 0.f); f0 = fmaf(a0, a0, f0); g0 += a0;
            float a1 = fmaxf(z[k + 1] - tau, 0.f); f1 = fmaf(a1, a1, f1); g1 += a1;
        }
        float f = f0 + f1, g = g0 + g1;
        f += __shfl_xor_sync(0xffffffffu, f, 1);
        g += __shfl_xor_sync(0xffffffffu, g, 1);
        tau += (f - 1.0f) / fmaxf(2.0f * g, 1e-12f);
    }

    #pragma unroll
    for (int k = 0; k < 64; ++k) {
        float a = fmaxf(z[k] - tau, 0.f);
        sm[(half * 64 + k) * 65 + col] = a * a;
    }
    __syncthreads();
    float* dst = g_WT + (size_t)mn * D_ * T_;
    for (int i = threadIdx.x; i < D_ * T_; i += 128)
        dst[i] = sm[(i >> 6) * 65 + (i & 63)];
}

// ---------------------------------------------------------------------------
// helper: split float4 into packed bf16 hi / lo pairs
// ---------------------------------------------------------------------------
__device__ __forceinline__ uint2 bf16split4(float4 v, uint2* lo) {
    __nv_bfloat16 h0 = __float2bfloat16(v.x), h1 = __float2bfloat16(v.y);
    __nv_bfloat16 h2 = __float2bfloat16(v.z), h3 = __float2bfloat16(v.w);
    __nv_bfloat16 l0 = __float2bfloat16(v.x - __bfloat162float(h0));
    __nv_bfloat16 l1 = __float2bfloat16(v.y - __bfloat162float(h1));
    __nv_bfloat16 l2 = __float2bfloat16(v.z - __bfloat162float(h2));
    __nv_bfloat16 l3 = __float2bfloat16(v.w - __bfloat162float(h3));
    uint2 hi;
    hi.x = (unsigned)__bfloat16_as_ushort(h0) | ((unsigned)__bfloat16_as_ushort(h1) << 16);
    hi.y = (unsigned)__bfloat16_as_ushort(h2) | ((unsigned)__bfloat16_as_ushort(h3) << 16);
    lo->x = (unsigned)__bfloat16_as_ushort(l0) | ((unsigned)__bfloat16_as_ushort(l1) << 16);
    lo->y = (unsigned)__bfloat16_as_ushort(l2) | ((unsigned)__bfloat16_as_ushort(l3) << 16);
    return hi;
}

// ---------------------------------------------------------------------------
// K2: priors GEMM (proven scalar f32x2 core) -> bf16 hi/lo [n][b][m][t].
//     Grid = 2*M_*N_: blockIdx = mn*2 + chunk (128 b's per block). 8b x 8t tile.
// ---------------------------------------------------------------------------
__global__ __launch_bounds__(128, 4) void k_priors(const float* __restrict__ x) {
    __shared__ __align__(16) float ws[D_ * 64];  // [d][t], rows 256B
    int mn = blockIdx.x >> 1;
    int chunk = blockIdx.x & 1;
    int m = mn >> 5, n = mn & 31;
    {
        const float4* wsrc = reinterpret_cast<const float4*>(g_WT + (size_t)mn * D_ * T_);
        float4* wd = reinterpret_cast<float4*>(ws);
        for (int i = threadIdx.x; i < D_ * T_ / 4; i += 128) wd[i] = wsrc[i];
    }
    __syncthreads();
    unsigned wsb = (unsigned)__cvta_generic_to_shared(ws);
    int tx = threadIdx.x & 7;
    int by = threadIdx.x >> 3;
    unsigned wA = wsb + (unsigned)tx * 16u;
    unsigned wB = wA + 128u;

    int b0 = chunk * 128 + by * 8;
    unsigned long long acc[8][4];
    #pragma unroll
    for (int bi = 0; bi < 8; ++bi)
        #pragma unroll
        for (int j = 0; j < 4; ++j) acc[bi][j] = 0ull;

    const float4* xb = reinterpret_cast<const float4*>(x + ((size_t)b0 * M_ + m) * D_);

    #pragma unroll 2
    for (int dq = 0; dq < 32; ++dq) {
        float4 xv[8];
        #pragma unroll
        for (int bi = 0; bi < 8; ++bi) xv[bi] = __ldg(xb + bi * (M_ * D_ / 4) + dq);
        #pragma unroll
        for (int dd = 0; dd < 4; ++dd) {
            unsigned long long a01, a23, b01, b23;
            unsigned rowoff = (unsigned)(dq * 4 + dd) * 256u;
            asm volatile("ld.shared.v2.b64 {%0,%1},[%2];" : "=l"(a01), "=l"(a23) : "r"(wA + rowoff));
            asm volatile("ld.shared.v2.b64 {%0,%1},[%2];" : "=l"(b01), "=l"(b23) : "r"(wB + rowoff));
            #pragma unroll
            for (int bi = 0; bi < 8; ++bi) {
                float xs = (dd == 0) ? xv[bi].x : (dd == 1) ? xv[bi].y
                         : (dd == 2) ? xv[bi].z : xv[bi].w;
                unsigned long long xp;
                asm("mov.b64 %0, {%1,%1};" : "=l"(xp) : "f"(xs));
                asm("fma.rn.f32x2 %0, %1, %2, %0;" : "+l"(acc[bi][0]) : "l"(xp), "l"(a01));
                asm("fma.rn.f32x2 %0, %1, %2, %0;" : "+l"(acc[bi][1]) : "l"(xp), "l"(a23));
                asm("fma.rn.f32x2 %0, %1, %2, %0;" : "+l"(acc[bi][2]) : "l"(xp), "l"(b01));
                asm("fma.rn.f32x2 %0, %1, %2, %0;" : "+l"(acc[bi][3]) : "l"(xp), "l"(b23));
            }
        }
    }
    #pragma unroll
    for (int bi = 0; bi < 8; ++bi) {
        float4 o0, o1;
        asm("mov.b64 {%0,%1}, %2;" : "=f"(o0.x), "=f"(o0.y) : "l"(acc[bi][0]));
        asm("mov.b64 {%0,%1}, %2;" : "=f"(o0.z), "=f"(o0.w) : "l"(acc[bi][1]));
        asm("mov.b64 {%0,%1}, %2;" : "=f"(o1.x), "=f"(o1.y) : "l"(acc[bi][2]));
        asm("mov.b64 {%0,%1}, %2;" : "=f"(o1.z), "=f"(o1.w) : "l"(acc[bi][3]));
        int b = b0 + bi;
        size_t base = (((size_t)n * B_ + b) * M_ + m) * T_;
        uint2 lo0, lo1;
        uint2 hi0 = bf16split4(o0, &lo0);
        uint2 hi1 = bf16split4(o1, &lo1);
        *(uint2*)(g_ph + base + 4 * tx)      = hi0;
        *(uint2*)(g_ph + base + 32 + 4 * tx) = hi1;
        *(uint2*)(g_pl + base + 4 * tx)      = lo0;
        *(uint2*)(g_pl + base + 32 + 4 * tx) = lo1;
    }
}

// ---------------------------------------------------------------------------
// K3: votes GEMM via mma.sync m16n8k16 bf16 + register epilogue.
//     One CTA per (n, b-pair): 256 threads / 8 warps, M=128 rows (2 b x 64 m),
//     N=128 l, K=64 t, 3 hi/lo products fused per fragment-load (B reuse).
//     Votes stay in registers: sigmoid in place, vbar via shfl {4,8,16} +
//     8x128 warp table, dispersion via shfl {1,2}. Then per-b softmax,
//     next_caps (ps fp32 from the live A images), layernorm.
//     smem (bytes): Ah 0 (18432) | Al 18432 | Bh 36864 | Bl 55296 |
//       table 73728 (4096) | vbar 77824 (1024) | wgt 78848 (512) |
//       prob 79360 (512) | ncs 79872 (512)  => 80384 total, 2 CTAs/SM.
// ---------------------------------------------------------------------------
#define K3_SMEM 80384

__global__ __launch_bounds__(256) void k_route(
    const float* __restrict__ thr, const float* __restrict__ gamma,
    const float* __restrict__ beta, float* __restrict__ out)
{
    extern __shared__ __align__(16) char smc[];
    unsigned abase = (unsigned)__cvta_generic_to_shared(smc);

    float* table = (float*)(smc + 73728);   // [8 warps][128 l]
    float* vbar  = (float*)(smc + 77824);   // [2][128]
    float* wgt   = (float*)(smc + 78848);   // [128] = [bb*64+m]
    float* prob  = (float*)(smc + 79360);   // [128]
    float* ncs   = (float*)(smc + 79872);   // [128]

    int tid = threadIdx.x;
    int lane = tid & 31, w = tid >> 5;
    int n = blockIdx.x >> 7, bp = blockIdx.x & 127;

    // stage A (ps hi/lo for b = 2bp, 2bp+1 -> rows bb*64+m) and B (lh hi/lo)
    {
        size_t pbase = (((size_t)n * B_ + 2 * bp) * M_) * T_;  // elements; 2 b's contiguous
        const uint4* sh = (const uint4*)(g_ph + pbase);
        const uint4* sl = (const uint4*)(g_pl + pbase);
        for (int i = tid; i < 1024; i += 256) {          // 128 rows x 8 uint4
            int r = i >> 3, q = i & 7;
            *(uint4*)(smc + r * 144 + q * 16) = sh[i];
            *(uint4*)(smc + 18432 + r * 144 + q * 16) = sl[i];
        }
        const uint4* th = (const uint4*)g_lhh;
        const uint4* tl = (const uint4*)g_lhl;
        for (int i = tid; i < 1024; i += 256) {          // 128 rows x 8 uint4
            int r = i >> 3, q = i & 7;
            *(uint4*)(smc + 36864 + r * 144 + q * 16) = th[i];
            *(uint4*)(smc + 55296 + r * 144 + q * 16) = tl[i];
        }
    }
    __syncthreads();

    // fragment addresses
    int m0 = w * 16;
    unsigned a_off = (unsigned)((m0 + (lane & 15)) * 144) + ((lane & 16) ? 16u : 0u);
    unsigned Ah_b = abase + a_off;
    unsigned Al_b = abase + 18432u + a_off;
    unsigned b_row = (unsigned)((lane & 7) + ((lane & 16) ? 8 : 0));
    unsigned b_col = (lane & 8) ? 16u : 0u;
    unsigned Bh_b = abase + 36864u + b_row * 144u + b_col;
    unsigned Bl_b = Bh_b + 18432u;

    float acc[16][4];
    #pragma unroll
    for (int nt = 0; nt < 16; ++nt)
        #pragma unroll
        for (int q = 0; q < 4; ++q) acc[nt][q] = 0.f;

    // fused GEMM: per (ks, np) load Ah/Al/Bh/Bl fragments once, 3 products
    #pragma unroll 1
    for (int ks = 0; ks < 4; ++ks) {
        unsigned ra_h[4], ra_l[4];
        asm volatile("ldmatrix.sync.aligned.m8n8.x4.shared.b16 {%0,%1,%2,%3},[%4];"
                     : "=r"(ra_h[0]), "=r"(ra_h[1]), "=r"(ra_h[2]), "=r"(ra_h[3])
                     : "r"(Ah_b + (unsigned)ks * 32u));
        asm volatile("ldmatrix.sync.aligned.m8n8.x4.shared.b16 {%0,%1,%2,%3},[%4];"
                     : "=r"(ra_l[0]), "=r"(ra_l[1]), "=r"(ra_l[2]), "=r"(ra_l[3])
                     : "r"(Al_b + (unsigned)ks * 32u));
        #pragma unroll
        for (int np = 0; np < 8; ++np) {
            unsigned rb_h[4], rb_l[4];
            unsigned boff = (unsigned)np * 2304u + (unsigned)ks * 32u;
            asm volatile("ldmatrix.sync.aligned.m8n8.x4.shared.b16 {%0,%1,%2,%3},[%4];"
                         : "=r"(rb_h[0]), "=r"(rb_h[1]), "=r"(rb_h[2]), "=r"(rb_h[3])
                         : "r"(Bh_b + boff));
            asm volatile("ldmatrix.sync.aligned.m8n8.x4.shared.b16 {%0,%1,%2,%3},[%4];"
                         : "=r"(rb_l[0]), "=r"(rb_l[1]), "=r"(rb_l[2]), "=r"(rb_l[3])
                         : "r"(Bl_b + boff));
            #pragma unroll
            for (int h = 0; h < 2; ++h) {  // n8 half: acc[2np+h], rb[2h],rb[2h+1]
                float* A0 = acc[2 * np + h];
                asm volatile(
                    "mma.sync.aligned.m16n8k16.row.col.f32.bf16.bf16.f32 "
                    "{%0,%1,%2,%3},{%4,%5,%6,%7},{%8,%9},{%0,%1,%2,%3};"
                    : "+f"(A0[0]), "+f"(A0[1]), "+f"(A0[2]), "+f"(A0[3])
                    : "r"(ra_h[0]), "r"(ra_h[1]), "r"(ra_h[2]), "r"(ra_h[3]),
                      "r"(rb_h[2 * h]), "r"(rb_h[2 * h + 1]));
                asm volatile(
                    "mma.sync.aligned.m16n8k16.row.col.f32.bf16.bf16.f32 "
                    "{%0,%1,%2,%3},{%4,%5,%6,%7},{%8,%9},{%0,%1,%2,%3};"
                    : "+f"(A0[0]), "+f"(A0[1]), "+f"(A0[2]), "+f"(A0[3])
                    : "r"(ra_h[0]), "r"(ra_h[1]), "r"(ra_h[2]), "r"(ra_h[3]),
                      "r"(rb_l[2 * h]), "r"(rb_l[2 * h + 1]));
                asm volatile(
                    "mma.sync.aligned.m16n8k16.row.col.f32.bf16.bf16.f32 "
                    "{%0,%1,%2,%3},{%4,%5,%6,%7},{%8,%9},{%0,%1,%2,%3};"
                    : "+f"(A0[0]), "+f"(A0[1]), "+f"(A0[2]), "+f"(A0[3])
                    : "r"(ra_l[0]), "r"(ra_l[1]), "r"(ra_l[2]), "r"(ra_l[3]),
                      "r"(rb_h[2 * h]), "r"(rb_h[2 * h + 1]));
            }
        }
    }

    // sigmoid in place: acc now = votes fragments
    #pragma unroll
    for (int nt = 0; nt < 16; ++nt)
        #pragma unroll
        for (int q = 0; q < 4; ++q)
            acc[nt][q] = 1.0f / (1.0f + __expf(-acc[nt][q]));

    // column sums over this warp's 16 rows: shfl over lane>>2 (bits 2..4)
    {
        float cs0[16], cs1[16];
        #pragma unroll
        for (int nt = 0; nt < 16; ++nt) {
            cs0[nt] = acc[nt][0] + acc[nt][2];
            cs1[nt] = acc[nt][1] + acc[nt][3];
        }
        #pragma unroll
        for (int s = 4; s <= 16; s <<= 1)
            #pragma unroll
            for (int nt = 0; nt < 16; ++nt) {
                cs0[nt] += __shfl_xor_sync(0xffffffffu, cs0[nt], s);
                cs1[nt] += __shfl_xor_sync(0xffffffffu, cs1[nt], s);
            }
        if (lane < 4) {
            #pragma unroll
            for (int nt = 0; nt < 16; ++nt)
                *(float2*)(table + w * 128 + nt * 8 + lane * 2) = make_float2(cs0[nt], cs1[nt]);
        }
    }
    __syncthreads();

    // vbar[bb][l] = (sum of 4 warp partials) / 64
    {
        int bb = tid >> 7, l = tid & 127;
        float s = table[(bb * 4 + 0) * 128 + l] + table[(bb * 4 + 1) * 128 + l]
                + table[(bb * 4 + 2) * 128 + l] + table[(bb * 4 + 3) * 128 + l];
        vbar[bb * 128 + l] = s * (1.0f / 64.0f);
    }
    __syncthreads();

    // dispersion from registers; reduce over lane&3 (column owners)
    {
        int bb = w >> 2;
        float dis0 = 0.f, dis1 = 0.f;
        #pragma unroll
        for (int nt = 0; nt < 16; ++nt) {
            int c = nt * 8 + (lane & 3) * 2;
            float2 vb = *(const float2*)(vbar + bb * 128 + c);
            float d;
            d = acc[nt][0] - vb.x; dis0 = fmaf(d, d, dis0);
            d = acc[nt][1] - vb.y; dis0 = fmaf(d, d, dis0);
            d = acc[nt][2] - vb.x; dis1 = fmaf(d, d, dis1);
            d = acc[nt][3] - vb.y; dis1 = fmaf(d, d, dis1);
        }
        dis0 += __shfl_xor_sync(0xffffffffu, dis0, 1);
        dis0 += __shfl_xor_sync(0xffffffffu, dis0, 2);
        dis1 += __shfl_xor_sync(0xffffffffu, dis1, 1);
        dis1 += __shfl_xor_sync(0xffffffffu, dis1, 2);
        if ((lane & 3) == 0) {
            int row0 = m0 + (lane >> 2);
            float tw0 = thr[(row0 & 63) * N_ + n];
            float tw1 = thr[((row0 + 8) & 63) * N_ + n];
            wgt[row0]     = fmaxf(fmaf(tw0, tw0, -dis0 * (1.0f / L_)), 0.0f);
            wgt[row0 + 8] = fmaxf(fmaf(tw1, tw1, -dis1 * (1.0f / L_)), 0.0f);
        }
    }
    __syncthreads();

    // softmax over M per bb
    if (tid < 128) {
        int bb = tid >> 6;
        float mxw = -3.0e38f;
        #pragma unroll 8
        for (int mm = 0; mm < 64; ++mm) mxw = fmaxf(mxw, wgt[bb * 64 + mm]);
        prob[tid] = __expf(wgt[tid] - mxw);
    }
    __syncthreads();

    // next_caps per (bb, t): ps fp32 from the live A images
    if (tid < 128) {
        int bb = tid >> 6, t = tid & 63;
        const __nv_bfloat16* Ah = (const __nv_bfloat16*)smc;
        const __nv_bfloat16* Al = (const __nv_bfloat16*)(smc + 18432);
        float psum = 0.f;
        #pragma unroll 8
        for (int mm = 0; mm < 64; ++mm) psum += prob[bb * 64 + mm];
        float nc = 0.f;
        #pragma unroll 4
        for (int mm = 0; mm < 64; ++mm) {
            int row = bb * 64 + mm;
            float p = __bfloat162float(Ah[row * 72 + t]) + __bfloat162float(Al[row * 72 + t]);
            nc = fmaf(prob[bb * 64 + mm], p, nc);
        }
        ncs[tid] = nc / psum;
    }
    __syncthreads();

    // layernorm over T per bb
    if (tid < 128) {
        int bb = tid >> 6, t = tid & 63;
        float mu = 0.f;
        #pragma unroll 8
        for (int t2 = 0; t2 < T_; ++t2) mu += ncs[bb * 64 + t2];
        mu *= (1.0f / T_);
        float var = 0.f;
        #pragma unroll 8
        for (int t2 = 0; t2 < T_; ++t2) {
            float dv = ncs[bb * 64 + t2] - mu;
            var = fmaf(dv, dv, var);
        }
        var *= (1.0f / T_);
        float y = (ncs[tid] - mu) * rsqrtf(var + 1e-5f) * gamma[t] + beta[t];
        out[((size_t)(2 * bp + bb) * N_ + n) * T_ + t] = y;
    }
}

// ---------------------------------------------------------------------------
// Launch
// ---------------------------------------------------------------------------
extern "C" void kernel_launch(void* const* d_in, const int* in_sizes, int n_in,
                              void* d_out, int out_size) {
    const float* x      = (const float*)d_in[0];
    const float* rw     = (const float*)d_in[1];
    const float* thr    = (const float*)d_in[2];
    const float* leaves = (const float*)d_in[3];
    const float* gamma  = (const float*)d_in[4];
    const float* beta   = (const float*)d_in[5];
    float* out = (float*)d_out;

    k_leaves<<<1, 128>>>(leaves);
    k_entmax<<<M_ * N_, 128>>>(rw);
    k_priors<<<M_ * N_ * 2, 128>>>(x);

    static int attr_set = 0;
    if (!attr_set) {
        cudaFuncSetAttribute(k_route, cudaFuncAttributeMaxDynamicSharedMemorySize, K3_SMEM);
        attr_set = 1;
    }
    k_route<<<N_ * 128, 256, K3_SMEM>>>(thr, gamma, beta, out);
}